// round 13
// baseline (speedup 1.0000x reference)
#include <cuda_runtime.h>
#include <cuda_bf16.h>
#include <cstdint>

#define TPB     512
#define TILE_M  128
#define DDIM    128
#define KCODES  128
#define MARGIN  0.01f

// ---- shared layout (bytes) ----
#define Z_OFF(b)   ((b) * 65536)            // fp32 z tile: 128 rows * 512B, x2 buffers
#define WP_OFF(p)  (131072 + (p) * 32768)   // bf16 W plane: 128 rows * 256B, hi/lo
#define CSH_OFF    196608                   // 128 floats
#define SIDX_OFF   197120                   // 128 ints
#define TMRG_OFF   197632                   // 128 rows * 2 halves * 16B top-2 records
#define SMEM_BYTES (197632 + 4096)

// swizzled addressing (conflict-free for the mma fragment patterns)
__device__ __forceinline__ uint32_t a_off(int m, int w64) {      // fp32 pairs, 8B units
    return (uint32_t)(m * 512 + ((w64 ^ ((m & 7) * 4)) * 8));
}
__device__ __forceinline__ uint32_t w_off(int n, int w32) {      // bf16 pairs, 4B units
    return (uint32_t)(n * 256 + ((w32 ^ ((n & 7) * 4)) * 4));
}

__device__ __forceinline__ uint32_t smem_u32(const void* p) {
    uint32_t a;
    asm("{ .reg .u64 t; cvta.to.shared.u64 t, %1; cvt.u32.u64 %0, t; }" : "=r"(a) : "l"(p));
    return a;
}
__device__ __forceinline__ uint32_t pack_bf16x2(float x0, float x1) {
    uint32_t r;
    asm("cvt.rn.bf16x2.f32 %0, %1, %2;" : "=r"(r) : "f"(x1), "f"(x0));
    return r;
}
__device__ __forceinline__ void split_pair(float x0, float x1, uint32_t& hi, uint32_t& lo) {
    hi = pack_bf16x2(x0, x1);
    float h0 = __uint_as_float(hi << 16);
    float h1 = __uint_as_float(hi & 0xffff0000u);
    lo = pack_bf16x2(x0 - h0, x1 - h1);
}
__device__ __forceinline__ void cp_async16(uint32_t dst, const void* src) {
    asm volatile("cp.async.cg.shared.global [%0], [%1], 16;" :: "r"(dst), "l"(src) : "memory");
}
#define CP_COMMIT() asm volatile("cp.async.commit_group;" ::: "memory")
#define CP_WAIT0()  asm volatile("cp.async.wait_group 0;" ::: "memory")

__device__ __forceinline__ void mma_bf16(float* d, const uint32_t* a, uint32_t b0, uint32_t b1) {
    asm volatile("mma.sync.aligned.m16n8k16.row.col.f32.bf16.bf16.f32 "
                 "{%0,%1,%2,%3}, {%4,%5,%6,%7}, {%8,%9}, {%0,%1,%2,%3};"
                 : "+f"(d[0]), "+f"(d[1]), "+f"(d[2]), "+f"(d[3])
                 : "r"(a[0]), "r"(a[1]), "r"(a[2]), "r"(a[3]), "r"(b0), "r"(b1));
}

__device__ __forceinline__ bool better(float v, int i, float v2, int i2) {
    return (v > v2) || (v == v2 && i < i2);
}

__device__ __forceinline__ void load_tile(const float* __restrict__ z, int t, int N,
                                          uint32_t sb, int buf, int tid) {
    const size_t rowbase = (size_t)t * TILE_M;
    #pragma unroll 2
    for (int i = tid; i < TILE_M * 32; i += TPB) {
        int m = i >> 5, ch = i & 31;
        if (rowbase + m < (size_t)N) {
            uint32_t dst = sb + Z_OFF(buf) + (uint32_t)(m * 512 + (((2 * ch) ^ ((m & 7) * 4)) * 8));
            cp_async16(dst, z + (rowbase + m) * DDIM + ch * 4);
        }
    }
}

__device__ float exact_sm(const char* zb, int rloc, const float* __restrict__ W, int k) {
    const float* wr = W + (size_t)k * DDIM;
    float s = 0.f;
    #pragma unroll 8
    for (int w = 0; w < 64; ++w) {
        float2 p = *(const float2*)(zb + a_off(rloc, w));
        s += p.x * __ldg(wr + 2 * w) + p.y * __ldg(wr + 2 * w + 1);
    }
    return s;
}

__global__ __launch_bounds__(TPB, 1) void vq_hmma_kernel(
    const float* __restrict__ z, const float* __restrict__ W,
    float* __restrict__ out, int N, int ntiles)
{
    extern __shared__ char smem[];
    const uint32_t sb = smem_u32(smem);
    const int tid  = threadIdx.x;
    const int wid  = tid >> 5, lane = tid & 31;
    const int g    = lane >> 2, c = lane & 3;
    const int rowg = wid >> 1;          // 0..7 : 16-row group
    const int hh   = wid & 1;           // code half: [hh*64, hh*64+64)

    float*  csh  = (float*)(smem + CSH_OFF);
    int*    sidx = (int*)(smem + SIDX_OFF);
    float4* tmrg = (float4*)(smem + TMRG_OFF);   // [row*2 + half] = {v1, i1, v2, i2}

    // ---- stage W split planes + csh (once) ----
    for (int i = tid; i < KCODES * 64; i += TPB) {
        int n = i >> 6, w = i & 63;
        float x0 = __ldg(W + n * DDIM + 2 * w);
        float x1 = __ldg(W + n * DDIM + 2 * w + 1);
        uint32_t hi, lo; split_pair(x0, x1, hi, lo);
        *(uint32_t*)(smem + WP_OFF(0) + w_off(n, w)) = hi;
        *(uint32_t*)(smem + WP_OFF(1) + w_off(n, w)) = lo;
    }
    if (tid < KCODES) {
        const float4* wr = (const float4*)(W + (size_t)tid * DDIM);
        float s = 0.f;
        #pragma unroll
        for (int q = 0; q < DDIM / 4; ++q) {
            float4 v = __ldg(wr + q);
            s += v.x * v.x + v.y * v.y + v.z * v.z + v.w * v.w;
        }
        csh[tid] = 0.5f * s;
    }
    __syncthreads();

    const int nct = gridDim.x;
    int t = blockIdx.x;
    int buf = 0;

    load_tile(z, t, N, sb, 0, tid);
    CP_COMMIT(); CP_WAIT0();
    __syncthreads();

    while (true) {
        const int tn = t + nct;
        const bool hn = tn < ntiles;
        if (hn) { load_tile(z, tn, N, sb, buf ^ 1, tid); CP_COMMIT(); }

        // ---- compute: warp owns rows [rowg*16,+16) x codes [hh*64,+64) ----
        float acc[8][4];
        #pragma unroll
        for (int nt = 0; nt < 8; ++nt)
            #pragma unroll
            for (int q = 0; q < 4; ++q) acc[nt][q] = 0.f;

        const char* zb  = smem + Z_OFF(buf);
        const char* wp0 = smem + WP_OFF(0);
        const char* wp1 = smem + WP_OFF(1);

        #pragma unroll 1
        for (int kt = 0; kt < 8; ++kt) {
            uint32_t Ah[4], Al[4];
            {
                int r0 = rowg * 16 + g;
                float2 p0 = *(const float2*)(zb + a_off(r0,     8 * kt + c));
                float2 p1 = *(const float2*)(zb + a_off(r0 + 8, 8 * kt + c));
                float2 p2 = *(const float2*)(zb + a_off(r0,     8 * kt + c + 4));
                float2 p3 = *(const float2*)(zb + a_off(r0 + 8, 8 * kt + c + 4));
                split_pair(p0.x, p0.y, Ah[0], Al[0]);
                split_pair(p1.x, p1.y, Ah[1], Al[1]);
                split_pair(p2.x, p2.y, Ah[2], Al[2]);
                split_pair(p3.x, p3.y, Ah[3], Al[3]);
            }
            #pragma unroll
            for (int nt = 0; nt < 8; ++nt) {
                int n = hh * 64 + 8 * nt + g;
                uint32_t bh0 = *(const uint32_t*)(wp0 + w_off(n, 8 * kt + c));
                uint32_t bh1 = *(const uint32_t*)(wp0 + w_off(n, 8 * kt + c + 4));
                uint32_t bl0 = *(const uint32_t*)(wp1 + w_off(n, 8 * kt + c));
                uint32_t bl1 = *(const uint32_t*)(wp1 + w_off(n, 8 * kt + c + 4));
                mma_bf16(acc[nt], Ah, bh0, bh1);
                mma_bf16(acc[nt], Ah, bl0, bl1);
                mma_bf16(acc[nt], Al, bh0, bh1);
            }
        }

        // ---- per-half top-2, merge across 4-lane group, stash to smem ----
        #pragma unroll
        for (int rh = 0; rh < 2; ++rh) {
            float v1 = -3.402823466e38f, v2 = -3.402823466e38f;
            int i1 = 0, i2 = 0;
            #pragma unroll
            for (int nt = 0; nt < 8; ++nt) {
                int k0 = hh * 64 + nt * 8 + c * 2;
                float s0 = acc[nt][rh * 2]     - csh[k0];
                float s1 = acc[nt][rh * 2 + 1] - csh[k0 + 1];
                if (s0 > v1)      { v2 = v1; i2 = i1; v1 = s0; i1 = k0; }
                else if (s0 > v2) { v2 = s0; i2 = k0; }
                if (s1 > v1)      { v2 = v1; i2 = i1; v1 = s1; i1 = k0 + 1; }
                else if (s1 > v2) { v2 = s1; i2 = k0 + 1; }
            }
            #pragma unroll
            for (int m_ = 1; m_ <= 2; m_ <<= 1) {
                float ov1 = __shfl_xor_sync(0xffffffffu, v1, m_);
                int   oi1 = __shfl_xor_sync(0xffffffffu, i1, m_);
                float ov2 = __shfl_xor_sync(0xffffffffu, v2, m_);
                int   oi2 = __shfl_xor_sync(0xffffffffu, i2, m_);
                if (better(ov1, oi1, v1, i1)) {
                    if (better(v1, i1, ov2, oi2)) { v2 = v1; i2 = i1; }
                    else                          { v2 = ov2; i2 = oi2; }
                    v1 = ov1; i1 = oi1;
                } else if (better(ov1, oi1, v2, i2)) {
                    v2 = ov1; i2 = oi1;
                }
            }
            if (c == 0) {
                int rloc = rowg * 16 + rh * 8 + g;
                float4 rec;
                rec.x = v1; rec.y = __int_as_float(i1);
                rec.z = v2; rec.w = __int_as_float(i2);
                tmrg[rloc * 2 + hh] = rec;
            }
        }
        __syncthreads();

        // ---- merge halves + margin rescue (one thread per row) ----
        if (tid < TILE_M) {
            float4 a = tmrg[tid * 2 + 0];
            float4 b = tmrg[tid * 2 + 1];
            float v1, v2; int i1, i2;
            // half-0 indices are all smaller: ties resolve to half 0
            if (better(a.x, __float_as_int(a.y), b.x, __float_as_int(b.y))) {
                v1 = a.x; i1 = __float_as_int(a.y);
                if (better(a.z, __float_as_int(a.w), b.x, __float_as_int(b.y))) {
                    v2 = a.z; i2 = __float_as_int(a.w);
                } else { v2 = b.x; i2 = __float_as_int(b.y); }
            } else {
                v1 = b.x; i1 = __float_as_int(b.y);
                if (better(a.x, __float_as_int(a.y), b.z, __float_as_int(b.w))) {
                    v2 = a.x; i2 = __float_as_int(a.y);
                } else { v2 = b.z; i2 = __float_as_int(b.w); }
            }
            int rg = t * TILE_M + tid;
            int choice = i1;
            if (rg < N && (v1 - v2) < MARGIN) {
                const char* zb = smem + Z_OFF(buf);
                float e1 = exact_sm(zb, tid, W, i1) - csh[i1];
                float e2 = exact_sm(zb, tid, W, i2) - csh[i2];
                if (better(e2, i2, e1, i1)) choice = i2;
            }
            sidx[tid] = choice;
        }
        __syncthreads();

        // ---- gather W[idx] and write both output halves (coalesced) ----
        {
            const int base = t * TILE_M;
            const int rows = min(TILE_M, N - base);
            float4* o1 = (float4*)out;
            float4* o2 = o1 + (size_t)N * (DDIM / 4);
            for (int i = tid; i < rows * (DDIM / 4); i += TPB) {
                int r = i >> 5, dq = i & 31;
                float4 v = __ldg((const float4*)(W + (size_t)sidx[r] * DDIM) + dq);
                size_t off = (size_t)(base + r) * (DDIM / 4) + dq;
                o1[off] = v;
                o2[off] = v;
            }
        }

        if (!hn) break;
        CP_WAIT0();
        __syncthreads();
        t = tn; buf ^= 1;
    }
}

extern "C" void kernel_launch(void* const* d_in, const int* in_sizes, int n_in,
                              void* d_out, int out_size) {
    const float* z = (const float*)d_in[0];
    const float* W = (const float*)d_in[1];
    int N = in_sizes[0] / DDIM;
    int ntiles = (N + TILE_M - 1) / TILE_M;

    int nsm = 148;
    cudaDeviceGetAttribute(&nsm, cudaDevAttrMultiProcessorCount, 0);

    cudaFuncSetAttribute(vq_hmma_kernel, cudaFuncAttributeMaxDynamicSharedMemorySize, SMEM_BYTES);
    int grid = ntiles < nsm ? ntiles : nsm;
    vq_hmma_kernel<<<grid, TPB, SMEM_BYTES>>>(z, W, (float*)d_out, N, ntiles);
}

// round 14
// speedup vs baseline: 1.0163x; 1.0163x over previous
#include <cuda_runtime.h>
#include <cuda_bf16.h>
#include <cstdint>

#define TPB     256
#define TILE_M  128
#define DDIM    128
#define KCODES  128
#define MARGIN  0.01f

// ---- shared layout (bytes) ----
#define Z_OFF(b)   ((b) * 65536)            // fp32 z tile: 128 rows * 512B, x2 buffers
#define WP_OFF(p)  (131072 + (p) * 32768)   // bf16 W plane: 128 rows * 256B, hi/lo
#define CSH_OFF    196608                   // 128 floats
#define SIDX_OFF   197120                   // 2 x 128 ints (double buffered)
#define TMRG_OFF   198144                   // 128 rows * 2 halves... (single buffer, reused)
#define SMEM_BYTES (198144 + 2048)

// swizzled addressing (conflict-free for the mma fragment patterns)
__device__ __forceinline__ uint32_t a_off(int m, int w64) {      // fp32 pairs, 8B units
    return (uint32_t)(m * 512 + ((w64 ^ ((m & 7) * 4)) * 8));
}
__device__ __forceinline__ uint32_t w_off(int n, int w32) {      // bf16 pairs, 4B units
    return (uint32_t)(n * 256 + ((w32 ^ ((n & 7) * 4)) * 4));
}

__device__ __forceinline__ uint32_t smem_u32(const void* p) {
    uint32_t a;
    asm("{ .reg .u64 t; cvta.to.shared.u64 t, %1; cvt.u32.u64 %0, t; }" : "=r"(a) : "l"(p));
    return a;
}
__device__ __forceinline__ uint32_t pack_bf16x2(float x0, float x1) {
    uint32_t r;
    asm("cvt.rn.bf16x2.f32 %0, %1, %2;" : "=r"(r) : "f"(x1), "f"(x0));
    return r;
}
__device__ __forceinline__ void split_pair(float x0, float x1, uint32_t& hi, uint32_t& lo) {
    hi = pack_bf16x2(x0, x1);
    float h0 = __uint_as_float(hi << 16);
    float h1 = __uint_as_float(hi & 0xffff0000u);
    lo = pack_bf16x2(x0 - h0, x1 - h1);
}
__device__ __forceinline__ void cp_async16(uint32_t dst, const void* src) {
    asm volatile("cp.async.cg.shared.global [%0], [%1], 16;" :: "r"(dst), "l"(src) : "memory");
}
#define CP_COMMIT() asm volatile("cp.async.commit_group;" ::: "memory")
#define CP_WAIT0()  asm volatile("cp.async.wait_group 0;" ::: "memory")

__device__ __forceinline__ void mma_bf16(float* d, const uint32_t* a, uint32_t b0, uint32_t b1) {
    asm volatile("mma.sync.aligned.m16n8k16.row.col.f32.bf16.bf16.f32 "
                 "{%0,%1,%2,%3}, {%4,%5,%6,%7}, {%8,%9}, {%0,%1,%2,%3};"
                 : "+f"(d[0]), "+f"(d[1]), "+f"(d[2]), "+f"(d[3])
                 : "r"(a[0]), "r"(a[1]), "r"(a[2]), "r"(a[3]), "r"(b0), "r"(b1));
}

__device__ __forceinline__ bool better(float v, int i, float v2, int i2) {
    return (v > v2) || (v == v2 && i < i2);
}

__device__ __forceinline__ void load_tile(const float* __restrict__ z, int t, int N,
                                          uint32_t sb, int buf, int tid) {
    const size_t rowbase = (size_t)t * TILE_M;
    #pragma unroll 4
    for (int i = tid; i < TILE_M * 32; i += TPB) {
        int m = i >> 5, ch = i & 31;
        if (rowbase + m < (size_t)N) {
            uint32_t dst = sb + Z_OFF(buf) + (uint32_t)(m * 512 + (((2 * ch) ^ ((m & 7) * 4)) * 8));
            cp_async16(dst, z + (rowbase + m) * DDIM + ch * 4);
        }
    }
}

__device__ float exact_sm(const char* zb, int rloc, const float* __restrict__ W, int k) {
    const float* wr = W + (size_t)k * DDIM;
    float s = 0.f;
    #pragma unroll 8
    for (int w = 0; w < 64; ++w) {
        float2 p = *(const float2*)(zb + a_off(rloc, w));
        s += p.x * __ldg(wr + 2 * w) + p.y * __ldg(wr + 2 * w + 1);
    }
    return s;
}

// Coalesced gather of W[idx[r]] into both output halves for one tile.
__device__ __forceinline__ void do_gather(const float* __restrict__ W,
                                          float* __restrict__ out,
                                          const int* __restrict__ idx,
                                          int t, int N, int tid) {
    const int base = t * TILE_M;
    const int rows = min(TILE_M, N - base);
    float4* o1 = (float4*)out;
    float4* o2 = o1 + (size_t)N * (DDIM / 4);
    #pragma unroll 4
    for (int i = tid; i < rows * (DDIM / 4); i += TPB) {
        int r = i >> 5, dq = i & 31;
        float4 v = __ldg((const float4*)(W + (size_t)idx[r] * DDIM) + dq);
        size_t off = (size_t)(base + r) * (DDIM / 4) + dq;
        o1[off] = v;
        o2[off] = v;
    }
}

__global__ __launch_bounds__(TPB, 1) void vq_hmma_kernel(
    const float* __restrict__ z, const float* __restrict__ W,
    float* __restrict__ out, int N, int ntiles)
{
    extern __shared__ char smem[];
    const uint32_t sb = smem_u32(smem);
    const int tid  = threadIdx.x;
    const int wid  = tid >> 5, lane = tid & 31;
    const int g    = lane >> 2, c = lane & 3;

    float*  csh  = (float*)(smem + CSH_OFF);
    int*    sidx = (int*)(smem + SIDX_OFF);        // [2][128]
    float4* tmrg = (float4*)(smem + TMRG_OFF);     // [128] {v1,i1,v2,i2} per-lane-group partials

    // ---- stage W split planes + csh (once) ----
    for (int i = tid; i < KCODES * 64; i += TPB) {
        int n = i >> 6, w = i & 63;
        float x0 = __ldg(W + n * DDIM + 2 * w);
        float x1 = __ldg(W + n * DDIM + 2 * w + 1);
        uint32_t hi, lo; split_pair(x0, x1, hi, lo);
        *(uint32_t*)(smem + WP_OFF(0) + w_off(n, w)) = hi;
        *(uint32_t*)(smem + WP_OFF(1) + w_off(n, w)) = lo;
    }
    if (tid < KCODES) {
        const float4* wr = (const float4*)(W + (size_t)tid * DDIM);
        float s = 0.f;
        #pragma unroll
        for (int q = 0; q < DDIM / 4; ++q) {
            float4 v = __ldg(wr + q);
            s += v.x * v.x + v.y * v.y + v.z * v.z + v.w * v.w;
        }
        csh[tid] = 0.5f * s;
    }
    __syncthreads();

    const int nct = gridDim.x;
    int t = blockIdx.x;
    int buf = 0, sbuf = 0;
    int tprev = -1;

    load_tile(z, t, N, sb, 0, tid);
    CP_COMMIT(); CP_WAIT0();
    __syncthreads();

    while (true) {
        const int tn = t + nct;
        const bool hn = tn < ntiles;
        if (hn) { load_tile(z, tn, N, sb, buf ^ 1, tid); CP_COMMIT(); }

        // ---- deferred gather of previous tile (overlaps with mma below) ----
        if (tprev >= 0) do_gather(W, out, sidx + (sbuf ^ 1) * TILE_M, tprev, N, tid);

        // ---- compute: warp wid owns rows [wid*16, wid*16+16) x 128 codes ----
        float acc[16][4];
        #pragma unroll
        for (int nt = 0; nt < 16; ++nt)
            #pragma unroll
            for (int q = 0; q < 4; ++q) acc[nt][q] = 0.f;

        const char* zb  = smem + Z_OFF(buf);
        const char* wp0 = smem + WP_OFF(0);
        const char* wp1 = smem + WP_OFF(1);

        #pragma unroll 2
        for (int kt = 0; kt < 8; ++kt) {
            uint32_t Ah[4], Al[4];
            {
                int r0 = wid * 16 + g;
                float2 p0 = *(const float2*)(zb + a_off(r0,     8 * kt + c));
                float2 p1 = *(const float2*)(zb + a_off(r0 + 8, 8 * kt + c));
                float2 p2 = *(const float2*)(zb + a_off(r0,     8 * kt + c + 4));
                float2 p3 = *(const float2*)(zb + a_off(r0 + 8, 8 * kt + c + 4));
                split_pair(p0.x, p0.y, Ah[0], Al[0]);
                split_pair(p1.x, p1.y, Ah[1], Al[1]);
                split_pair(p2.x, p2.y, Ah[2], Al[2]);
                split_pair(p3.x, p3.y, Ah[3], Al[3]);
            }
            #pragma unroll
            for (int nt = 0; nt < 16; ++nt) {
                int n = 8 * nt + g;
                uint32_t bh0 = *(const uint32_t*)(wp0 + w_off(n, 8 * kt + c));
                uint32_t bh1 = *(const uint32_t*)(wp0 + w_off(n, 8 * kt + c + 4));
                uint32_t bl0 = *(const uint32_t*)(wp1 + w_off(n, 8 * kt + c));
                uint32_t bl1 = *(const uint32_t*)(wp1 + w_off(n, 8 * kt + c + 4));
                mma_bf16(acc[nt], Ah, bh0, bh1);
                mma_bf16(acc[nt], Ah, bl0, bl1);
                mma_bf16(acc[nt], Al, bh0, bh1);
            }
        }

        // ---- epilogue: top-2 per row, merge across 4-lane group ----
        #pragma unroll
        for (int rh = 0; rh < 2; ++rh) {
            float v1 = -3.402823466e38f, v2 = -3.402823466e38f;
            int i1 = 0, i2 = 0;
            #pragma unroll
            for (int nt = 0; nt < 16; ++nt) {
                int k0 = nt * 8 + c * 2;
                float s0 = acc[nt][rh * 2]     - csh[k0];
                float s1 = acc[nt][rh * 2 + 1] - csh[k0 + 1];
                if (s0 > v1)      { v2 = v1; i2 = i1; v1 = s0; i1 = k0; }
                else if (s0 > v2) { v2 = s0; i2 = k0; }
                if (s1 > v1)      { v2 = v1; i2 = i1; v1 = s1; i1 = k0 + 1; }
                else if (s1 > v2) { v2 = s1; i2 = k0 + 1; }
            }
            #pragma unroll
            for (int m_ = 1; m_ <= 2; m_ <<= 1) {
                float ov1 = __shfl_xor_sync(0xffffffffu, v1, m_);
                int   oi1 = __shfl_xor_sync(0xffffffffu, i1, m_);
                float ov2 = __shfl_xor_sync(0xffffffffu, v2, m_);
                int   oi2 = __shfl_xor_sync(0xffffffffu, i2, m_);
                if (better(ov1, oi1, v1, i1)) {
                    if (better(v1, i1, ov2, oi2)) { v2 = v1; i2 = i1; }
                    else                          { v2 = ov2; i2 = oi2; }
                    v1 = ov1; i1 = oi1;
                } else if (better(ov1, oi1, v2, i2)) {
                    v2 = ov1; i2 = oi1;
                }
            }
            if (c == 0) {
                int rloc = wid * 16 + rh * 8 + g;
                int rg   = t * TILE_M + rloc;
                int choice = i1;
                if (rg < N && (v1 - v2) < MARGIN) {
                    float e1 = exact_sm(zb, rloc, W, i1) - csh[i1];
                    float e2 = exact_sm(zb, rloc, W, i2) - csh[i2];
                    if (better(e2, i2, e1, i1)) choice = i2;
                }
                sidx[sbuf * TILE_M + rloc] = choice;
            }
        }

        if (!hn) {
            __syncthreads();
            do_gather(W, out, sidx + sbuf * TILE_M, t, N, tid);
            break;
        }
        CP_WAIT0();
        __syncthreads();          // sidx visible + new z buffer ready + old buf free
        tprev = t; t = tn; buf ^= 1; sbuf ^= 1;
    }
}

extern "C" void kernel_launch(void* const* d_in, const int* in_sizes, int n_in,
                              void* d_out, int out_size) {
    const float* z = (const float*)d_in[0];
    const float* W = (const float*)d_in[1];
    int N = in_sizes[0] / DDIM;
    int ntiles = (N + TILE_M - 1) / TILE_M;

    int nsm = 148;
    cudaDeviceGetAttribute(&nsm, cudaDevAttrMultiProcessorCount, 0);

    cudaFuncSetAttribute(vq_hmma_kernel, cudaFuncAttributeMaxDynamicSharedMemorySize, SMEM_BYTES);
    int grid = ntiles < nsm ? ntiles : nsm;
    vq_hmma_kernel<<<grid, TPB, SMEM_BYTES>>>(z, W, (float*)d_out, N, ntiles);
}